// round 4
// baseline (speedup 1.0000x reference)
#include <cuda_runtime.h>

#define H     20
#define SEQ   512
#define NB    4096
#define WARPS 4        // warps per block
#define BPW   2        // batches per warp (ILP)
#define BPB   (WARPS * BPW)

typedef unsigned long long u64;

__device__ __forceinline__ u64 pack2(float a, float b) {
    u64 r; asm("mov.b64 %0, {%1,%2};" : "=l"(r) : "f"(a), "f"(b)); return r;
}
__device__ __forceinline__ void unpack2(u64 v, float& a, float& b) {
    asm("mov.b64 {%0,%1}, %2;" : "=f"(a), "=f"(b) : "l"(v));
}
// Blackwell packed fp32 FMA (f32x2, PTX-only)
__device__ __forceinline__ u64 fma2(u64 a, u64 b, u64 c) {
    u64 d; asm("fma.rn.f32x2 %0, %1, %2, %3;" : "=l"(d) : "l"(a), "l"(b), "l"(c)); return d;
}
__device__ __forceinline__ u64 add2(u64 a, u64 b) {
    u64 d; asm("add.rn.f32x2 %0, %1, %2;" : "=l"(d) : "l"(a), "l"(b)); return d;
}
__device__ __forceinline__ float ex2_(float v) {
    float r; asm("ex2.approx.f32 %0, %1;" : "=f"(r) : "f"(v)); return r;
}
__device__ __forceinline__ float rcp_(float v) {
    float r; asm("rcp.approx.f32 %0, %1;" : "=f"(r) : "f"(v)); return r;
}
#define L2E 1.4426950408889634f
__device__ __forceinline__ float sigmoidf_(float v) {   // 2 MUFU + FMUL + FADD
    return rcp_(1.0f + ex2_(v * -L2E));
}
__device__ __forceinline__ float tanhf_(float v) {      // 2 MUFU + FMUL + FADD + FFMA
    return fmaf(2.0f, rcp_(1.0f + ex2_(v * -2.0f * L2E)), -1.0f);
}

__global__ __launch_bounds__(128, 3) void lstm_fused(
    const float* __restrict__ x,     const float* __restrict__ W_ih,
    const float* __restrict__ W_hh,  const float* __restrict__ b_ih,
    const float* __restrict__ b_hh,  const float* __restrict__ W_lin,
    const float* __restrict__ b_lin, float* __restrict__ out)
{
    // Per-warp double-buffered h, duplicated {h,h} so LDS gives packed f32x2.
    __shared__ __align__(16) float2 hbuf[WARPS][2][BPW][H];
    __shared__ float xs[BPB * SEQ];          // whole x rows for this block (16 KB)

    const int warp = threadIdx.x >> 5;
    const int lane = threadIdx.x & 31;
    const int bbase = blockIdx.x * BPB;
    const int j = (lane < H) ? lane : (H - 1);

    // Cooperative, coalesced preload of x for all 8 batches of this block.
    for (int i = threadIdx.x; i < BPB * SEQ; i += blockDim.x)
        xs[i] = x[(size_t)bbase * SEQ + i];

    // Recurrent weights: lane j owns gate rows j(i), H+j(f), 2H+j(g), 3H+j(o),
    // packed (i,f) and (g,o). Shared by both batches -> 80 regs total.
    u64 wif[H], wgo[H];
#pragma unroll
    for (int k = 0; k < H; ++k) {
        wif[k] = pack2(W_hh[j * H + k],           W_hh[(H + j) * H + k]);
        wgo[k] = pack2(W_hh[(2 * H + j) * H + k], W_hh[(3 * H + j) * H + k]);
    }
    const u64 bif  = pack2(b_ih[j] + b_hh[j],             b_ih[H + j] + b_hh[H + j]);
    const u64 bgo  = pack2(b_ih[2 * H + j] + b_hh[2 * H + j],
                           b_ih[3 * H + j] + b_hh[3 * H + j]);
    const u64 wxif = pack2(W_ih[j],         W_ih[H + j]);
    const u64 wxgo = pack2(W_ih[2 * H + j], W_ih[3 * H + j]);
    const float wl = (lane < H) ? W_lin[lane] : 0.0f;
    const float bl = b_lin[0];

    if (lane < H) {
        hbuf[warp][0][0][lane] = make_float2(0.0f, 0.0f);
        hbuf[warp][0][1][lane] = make_float2(0.0f, 0.0f);
    }
    __syncthreads();   // covers xs preload + h init

    float c0 = 0.0f, c1 = 0.0f;
    const float* x0 = xs + (warp * BPW + 0) * SEQ;
    const float* x1 = xs + (warp * BPW + 1) * SEQ;
    float* ob = out + (size_t)(bbase + warp * BPW) * SEQ;

#pragma unroll 2
    for (int t = 0; t < SEQ; ++t) {
        const int rb = t & 1;
        const longlong2* hp0 = (const longlong2*)&hbuf[warp][rb][0][0];
        const longlong2* hp1 = (const longlong2*)&hbuf[warp][rb][1][0];

        float xt0 = x0[t], xt1 = x1[t];
        u64 x20 = pack2(xt0, xt0), x21 = pack2(xt1, xt1);

        u64 z = pack2(0.0f, 0.0f);
        u64 aIF0 = bif, bIF0 = z, aGO0 = bgo, bGO0 = z;
        u64 aIF1 = bif, bIF1 = z, aGO1 = bgo, bGO1 = z;
#pragma unroll
        for (int q = 0; q < H / 2; ++q) {
            longlong2 ha = hp0[q];               // {h2q,h2q, h2q+1,h2q+1} batch0
            longlong2 hb = hp1[q];               // batch1
            u64 h0a = (u64)ha.x, h1a = (u64)ha.y;
            u64 h0b = (u64)hb.x, h1b = (u64)hb.y;
            aIF0 = fma2(h0a, wif[2 * q],     aIF0);
            bIF0 = fma2(h1a, wif[2 * q + 1], bIF0);
            aGO0 = fma2(h0a, wgo[2 * q],     aGO0);
            bGO0 = fma2(h1a, wgo[2 * q + 1], bGO0);
            aIF1 = fma2(h0b, wif[2 * q],     aIF1);
            bIF1 = fma2(h1b, wif[2 * q + 1], bIF1);
            aGO1 = fma2(h0b, wgo[2 * q],     aGO1);
            bGO1 = fma2(h1b, wgo[2 * q + 1], bGO1);
        }
        u64 gIF0 = fma2(x20, wxif, add2(aIF0, bIF0));
        u64 gGO0 = fma2(x20, wxgo, add2(aGO0, bGO0));
        u64 gIF1 = fma2(x21, wxif, add2(aIF1, bIF1));
        u64 gGO1 = fma2(x21, wxgo, add2(aGO1, bGO1));

        float gi0, gf0, gg0, go0, gi1, gf1, gg1, go1;
        unpack2(gIF0, gi0, gf0); unpack2(gGO0, gg0, go0);
        unpack2(gIF1, gi1, gf1); unpack2(gGO1, gg1, go1);

        float iv0 = sigmoidf_(gi0), fv0 = sigmoidf_(gf0);
        float gv0 = tanhf_(gg0),    ov0 = sigmoidf_(go0);
        float iv1 = sigmoidf_(gi1), fv1 = sigmoidf_(gf1);
        float gv1 = tanhf_(gg1),    ov1 = sigmoidf_(go1);

        c0 = fmaf(fv0, c0, iv0 * gv0);
        c1 = fmaf(fv1, c1, iv1 * gv1);
        float h0 = ov0 * tanhf_(c0);
        float h1 = ov1 * tanhf_(c1);

        if (lane < H) {
            hbuf[warp][rb ^ 1][0][lane] = make_float2(h0, h0);
            hbuf[warp][rb ^ 1][1][lane] = make_float2(h1, h1);
        }
        __syncwarp();

        // Linear head for both batches (off the recurrence critical path).
        float v0 = h0 * wl, v1 = h1 * wl;
#pragma unroll
        for (int off = 16; off; off >>= 1) {
            v0 += __shfl_xor_sync(0xffffffffu, v0, off);
            v1 += __shfl_xor_sync(0xffffffffu, v1, off);
        }
        if (lane == 0) {
            ob[t]       = v0 + bl;
            ob[SEQ + t] = v1 + bl;
        }
    }
}

extern "C" void kernel_launch(void* const* d_in, const int* in_sizes, int n_in,
                              void* d_out, int out_size) {
    const float* x     = (const float*)d_in[0];
    const float* W_ih  = (const float*)d_in[1];
    const float* W_hh  = (const float*)d_in[2];
    const float* b_ih  = (const float*)d_in[3];
    const float* b_hh  = (const float*)d_in[4];
    const float* W_lin = (const float*)d_in[5];
    const float* b_lin = (const float*)d_in[6];
    float* out = (float*)d_out;

    lstm_fused<<<NB / BPB, WARPS * 32>>>(x, W_ih, W_hh, b_ih, b_hh, W_lin, b_lin, out);
}

// round 7
// speedup vs baseline: 1.1413x; 1.1413x over previous
#include <cuda_runtime.h>

#define H       20
#define SEQ     512
#define NB      4096
#define BPB     6                 // batches per block (120 compute lanes + 8 head lanes)
#define THREADS 128
#define GRID    ((NB + BPB - 1) / BPB)   // 683

typedef unsigned long long u64;

__device__ __forceinline__ u64 pack2(float a, float b) {
    u64 r; asm("mov.b64 %0, {%1,%2};" : "=l"(r) : "f"(a), "f"(b)); return r;
}
__device__ __forceinline__ void unpack2(u64 v, float& a, float& b) {
    asm("mov.b64 {%0,%1}, %2;" : "=f"(a), "=f"(b) : "l"(v));
}
// Blackwell packed fp32 math (f32x2, PTX-only)
__device__ __forceinline__ u64 fma2(u64 a, u64 b, u64 c) {
    u64 d; asm("fma.rn.f32x2 %0, %1, %2, %3;" : "=l"(d) : "l"(a), "l"(b), "l"(c)); return d;
}
__device__ __forceinline__ u64 add2(u64 a, u64 b) {
    u64 d; asm("add.rn.f32x2 %0, %1, %2;" : "=l"(d) : "l"(a), "l"(b)); return d;
}
__device__ __forceinline__ float ex2_(float v) {
    float r; asm("ex2.approx.f32 %0, %1;" : "=f"(r) : "f"(v)); return r;
}
__device__ __forceinline__ float rcp_(float v) {
    float r; asm("rcp.approx.f32 %0, %1;" : "=f"(r) : "f"(v)); return r;
}
#define L2E 1.4426950408889634f
__device__ __forceinline__ float sigmoidf_(float v) {
    return rcp_(1.0f + ex2_(v * -L2E));
}
__device__ __forceinline__ float tanhf_(float v) {
    return fmaf(2.0f, rcp_(1.0f + ex2_(v * -2.0f * L2E)), -1.0f);
}

__global__ __launch_bounds__(THREADS, 5) void lstm_fused(
    const float* __restrict__ x,     const float* __restrict__ W_ih,
    const float* __restrict__ W_hh,  const float* __restrict__ b_ih,
    const float* __restrict__ b_hh,  const float* __restrict__ W_lin,
    const float* __restrict__ b_lin, float* __restrict__ out)
{
    // (g,o) recurrent weights, shared by all batches. Row pad 22 u64 = 176 B
    // = 11 quads (odd) -> conflict-free LDS.128 across 20 distinct rows.
    __shared__ __align__(16) u64    wgo_s[H][22];
    // double-buffered h, duplicated {h,h} so LDS.128 feeds fma2 directly
    __shared__ __align__(16) float2 hbuf[2][BPB][H];
    // double-buffered h*W_lin partials for the head lanes (pad 24 -> 96B rows)
    __shared__ __align__(16) float  psum[2][BPB][24];
    __shared__ float xs[BPB * SEQ];   // staged x rows (12 KB)

    const int tid  = threadIdx.x;
    const int b    = tid / H;               // local batch  (compute lanes)
    const int j    = tid % H;               // hidden unit  (compute lanes)
    const bool comp = tid < BPB * H;        // 120 compute lanes
    const int  hs   = tid - BPB * H;        // head slot 0..7 on spare lanes
    const bool hact = (hs >= 0) && (hs < BPB) && (blockIdx.x * BPB + hs < NB);

    // Stage x for all 6 batches (coalesced; clamp out-of-range batch).
    for (int i = tid; i < BPB * SEQ; i += THREADS) {
        int gbx = blockIdx.x * BPB + (i >> 9);
        if (gbx > NB - 1) gbx = NB - 1;
        xs[i] = x[(size_t)gbx * SEQ + (i & (SEQ - 1))];
    }
    // Stage packed (g,o) weights.
    for (int idx = tid; idx < H * H; idx += THREADS) {
        int jj = idx / H, kk = idx % H;
        wgo_s[jj][kk] = pack2(W_hh[(2 * H + jj) * H + kk],
                              W_hh[(3 * H + jj) * H + kk]);
    }

    // Per-lane registers: (i,f) weights + biases + input weights + head weight.
    u64 wif[H];
    u64 bif = 0, bgo = 0, wxif = 0, wxgo = 0;
    float wl = 0.0f;
    if (comp) {
#pragma unroll
        for (int k = 0; k < H; ++k)
            wif[k] = pack2(W_hh[j * H + k], W_hh[(H + j) * H + k]);
        bif  = pack2(b_ih[j] + b_hh[j],             b_ih[H + j] + b_hh[H + j]);
        bgo  = pack2(b_ih[2 * H + j] + b_hh[2 * H + j],
                     b_ih[3 * H + j] + b_hh[3 * H + j]);
        wxif = pack2(W_ih[j],         W_ih[H + j]);
        wxgo = pack2(W_ih[2 * H + j], W_ih[3 * H + j]);
        wl   = W_lin[j];
        hbuf[0][b][j] = make_float2(0.0f, 0.0f);
    }
    const float bl = b_lin[0];
    float* ohead = hact ? (out + (size_t)(blockIdx.x * BPB + hs) * SEQ) : out;
    const longlong2* wp = (const longlong2*)&wgo_s[comp ? j : 0][0];
    const float* xrow = xs + ((comp ? b : 0) << 9);

    __syncthreads();

    float c = 0.0f;

#pragma unroll 2
    for (int t = 0; t < SEQ; ++t) {
        const int r = t & 1, w = r ^ 1;
        if (comp) {
            const longlong2* hp = (const longlong2*)&hbuf[r][b][0];
            float xt = xrow[t];
            u64 x2 = pack2(xt, xt);

            u64 z = pack2(0.0f, 0.0f);
            u64 aIF = bif, bIF = z, aGO = bgo, bGO = z;
#pragma unroll
            for (int q = 0; q < H / 2; ++q) {
                longlong2 hh = hp[q];     // {h2q,h2q},{h2q+1,h2q+1} broadcast
                longlong2 ww = wp[q];     // {wg,wo} pairs, conflict-free
                aIF = fma2((u64)hh.x, wif[2 * q],     aIF);
                bIF = fma2((u64)hh.y, wif[2 * q + 1], bIF);
                aGO = fma2((u64)hh.x, (u64)ww.x, aGO);
                bGO = fma2((u64)hh.y, (u64)ww.y, bGO);
            }
            u64 gIF = fma2(x2, wxif, add2(aIF, bIF));
            u64 gGO = fma2(x2, wxgo, add2(aGO, bGO));

            float gi, gf, gg, go;
            unpack2(gIF, gi, gf);
            unpack2(gGO, gg, go);
            float iv = sigmoidf_(gi);
            float fv = sigmoidf_(gf);
            float gv = tanhf_(gg);
            float ov = sigmoidf_(go);
            c = fmaf(fv, c, iv * gv);
            float h = ov * tanhf_(c);

            hbuf[w][b][j] = make_float2(h, h);
            psum[w][b][j] = h * wl;
        }
        __syncthreads();
        if (hact) {
            // 20 partials -> packed add2 tree (5 LDS.128 + 9 add2)
            const ulonglong2* pq = (const ulonglong2*)&psum[w][hs][0];
            ulonglong2 p0 = pq[0], p1 = pq[1], p2 = pq[2], p3 = pq[3], p4 = pq[4];
            u64 s0 = add2((u64)p0.x, (u64)p0.y);
            u64 s1 = add2((u64)p1.x, (u64)p1.y);
            u64 s2 = add2((u64)p2.x, (u64)p2.y);
            u64 s3 = add2((u64)p3.x, (u64)p3.y);
            u64 s4 = add2((u64)p4.x, (u64)p4.y);
            u64 s = add2(add2(add2(s0, s1), add2(s2, s3)), s4);
            float lo, hi;
            unpack2(s, lo, hi);
            ohead[t] = lo + hi + bl;
        }
    }
}

extern "C" void kernel_launch(void* const* d_in, const int* in_sizes, int n_in,
                              void* d_out, int out_size) {
    const float* x     = (const float*)d_in[0];
    const float* W_ih  = (const float*)d_in[1];
    const float* W_hh  = (const float*)d_in[2];
    const float* b_ih  = (const float*)d_in[3];
    const float* b_hh  = (const float*)d_in[4];
    const float* W_lin = (const float*)d_in[5];
    const float* b_lin = (const float*)d_in[6];
    float* out = (float*)d_out;

    lstm_fused<<<GRID, THREADS>>>(x, W_ih, W_hh, b_ih, b_hh, W_lin, b_lin, out);
}